// round 7
// baseline (speedup 1.0000x reference)
#include <cuda_runtime.h>
#include <cstddef>

// Problem constants
#define NB   16
#define NT   64
#define NF0  8
#define NN   100
#define BT   (NB * NT)            // 1024
#define ROWSTRIDE (NF0 * NN)      // 800 floats per (b,t) slice
#define SLAB ((size_t)BT * ROWSTRIDE)  // 819200 floats per k-slab

// Diffusion scratch: z_k for k = 1..15 at slab k-1.
// Triangular region t<k is never written; head substitutes zeros there.
__device__ float g_z[15 * BT * ROWSTRIDE];   // ~49.15 MB

// ---- packed f32x2 helpers (Blackwell: 1 instr = 2 fp32 FMAs, rn each) ----
typedef unsigned long long ull;

__device__ __forceinline__ ull pack2(float lo, float hi) {
    ull r; asm("mov.b64 %0, {%1,%2};" : "=l"(r) : "f"(lo), "f"(hi)); return r;
}
__device__ __forceinline__ void unpack2(ull v, float& lo, float& hi) {
    asm("mov.b64 {%0,%1}, %2;" : "=f"(lo), "=f"(hi) : "l"(v));
}
__device__ __forceinline__ ull ffma2(ull a, ull b, ull c) {
    ull d; asm("fma.rn.f32x2 %0, %1, %2, %3;" : "=l"(d) : "l"(a), "l"(b), "l"(c));
    return d;
}

// ---------------------------------------------------------------------------
// Diffusion step k: z_k[b,t] = z_{k-1}[b,t-1] @ S[b,t]  (skip t<k entirely).
// One block per (b,t), 256 threads (200 active), tile 1 f-row x 4 m-cols.
// S rows streamed as 16B packed pairs; inner loop = 2 x fma.f32x2.
// ---------------------------------------------------------------------------
__global__ __launch_bounds__(256)
void diffuse_step_kernel(const float* __restrict__ x,
                         const float* __restrict__ S,
                         int k)
{
    int bt  = blockIdx.x;          // b*64 + t
    int t   = bt & 63;
    if (t < k) return;             // zero region: never stored
    int tid = threadIdx.x;

    const float* src = (k == 1)
        ? (x + (size_t)(bt - 1) * ROWSTRIDE)
        : (g_z + (size_t)(k - 2) * SLAB + (size_t)(bt - 1) * ROWSTRIDE);

    __shared__ float Ash[ROWSTRIDE];
    for (int i = tid; i < ROWSTRIDE; i += 256) Ash[i] = src[i];
    __syncthreads();

    if (tid < 200) {
        int mg = tid % 25;                       // m-quad
        int f  = tid / 25;                       // f-row 0..7
        int m0 = mg * 4;
        const float* A0 = Ash + f * NN;
        const float* Sp = S + (size_t)bt * (NN * NN) + m0;

        ull acc01 = 0ull, acc23 = 0ull;          // (m0,m0+1), (m0+2,m0+3)
        #pragma unroll 10
        for (int n = 0; n < NN; n++) {
            ulonglong2 sv = *reinterpret_cast<const ulonglong2*>(Sp + (size_t)n * NN);
            float va = A0[n];
            ull va2 = pack2(va, va);
            acc01 = ffma2(va2, sv.x, acc01);
            acc23 = ffma2(va2, sv.y, acc23);
        }
        float a0, a1, a2, a3;
        unpack2(acc01, a0, a1); unpack2(acc23, a2, a3);
        float* d = g_z + (size_t)(k - 1) * SLAB + (size_t)bt * ROWSTRIDE
                 + f * NN + m0;
        d[0] = a0; d[1] = a1; d[2] = a2; d[3] = a3;
    }
}

// ---------------------------------------------------------------------------
// Fused head: gather z row [8][16] -> conv1(K=4)+relu+pool2 -> [32][6]
//             -> conv2(K=3)+relu+pool2 -> [64][2] -> fc1(128->64)+relu
//             -> fc2(64->5) -> out[b,t,o,n]
// 32 rows/block, 256 threads. All conv/fc inner loops use fma.rn.f32x2
// (halves FMA-pipe issue, which is the measured floor).
// Smem (floats): [0,4128)        zsh (32x129), reused as y2sh
//                [4128,10304)    y1sh (32x193); after conv2: hsh (32x66)
//                [10304,11328)   w1   [11328,11360) b1
//                [11360,17504)   w2   [17504,17568) b2
// After conv2, fc weights staged into the dead region:
//   fc1wp (packed ull[32*128]) [6240,14432), fc1b [14464,14528),
//   fc2w [14528,14848), fc2b [14848,14853)
// ---------------------------------------------------------------------------
#define ZS   129
#define Y1S  193
#define Y2S  129
#define HS   66
#define OFF_Y1   4128
#define OFF_W1   10304
#define OFF_B1   11328
#define OFF_W2   11360
#define OFF_B2   17504
#define OFF_FC1W 6240
#define OFF_FC1B 14464
#define OFF_FC2W 14528
#define OFF_FC2B 14848
#define SMEM_FLOATS 17568

__global__ __launch_bounds__(256, 2)
void head_kernel(const float* __restrict__ x,
                 const float* __restrict__ w1g, const float* __restrict__ b1g,
                 const float* __restrict__ w2g, const float* __restrict__ b2g,
                 const float* __restrict__ f1wg, const float* __restrict__ f1bg,
                 const float* __restrict__ f2wg, const float* __restrict__ f2bg,
                 float* __restrict__ out)
{
    extern __shared__ float sm[];
    float* zsh  = sm;
    float* y2sh = sm;                 // reuses zsh region after conv1
    float* y1sh = sm + OFF_Y1;
    float* hsh  = sm + OFF_Y1;        // aliases y1sh front (dead after conv2)
    float* w1sh = sm + OFF_W1;
    float* b1sh = sm + OFF_B1;
    float* w2sh = sm + OFF_W2;
    float* b2sh = sm + OFF_B2;

    int tid  = threadIdx.x;
    int row0 = blockIdx.x * 32;       // global row = (b*T + t)*N + n

    // ---- stage 0: gather z tile (32 rows x 8 f x 16 k = 4096) + conv weights ----
    for (int i = tid; i < 4096; i += 256) {
        int r  = i & 31;
        int kf = i >> 5;              // 0..127
        int f  = kf >> 4;             // 0..7
        int k  = kf & 15;             // 0..15
        int R  = row0 + r;
        int n  = R % NN;
        int bt = R / NN;
        float v;
        if (k == 0) {
            v = x[(size_t)bt * ROWSTRIDE + f * NN + n];
        } else if ((bt & 63) < k) {
            v = 0.f;                  // triangular zero region (never stored)
        } else {
            v = g_z[(size_t)(k - 1) * SLAB + (size_t)bt * ROWSTRIDE + f * NN + n];
        }
        zsh[r * ZS + f * 16 + k] = v;
    }
    for (int i = tid; i < 1024; i += 256) w1sh[i] = w1g[i];
    if (tid < 32) b1sh[tid] = b1g[tid];
    for (int i = tid; i < 6144; i += 256) w2sh[i] = w2g[i];
    if (tid < 64) b2sh[tid] = b2g[tid];
    __syncthreads();

    // ---- conv1 + relu + maxpool2 : thread = (r, 4 channels), packed l-pairs ----
    {
        int r = tid & 31, fg = tid >> 5;         // fg in [0,8): channels fg*4..+3
        ull acc2[4][6];                          // (l=2p, 2p+1) packed
        #pragma unroll
        for (int c = 0; c < 4; c++)
            #pragma unroll
            for (int p = 0; p < 6; p++) acc2[c][p] = 0ull;

        #pragma unroll
        for (int f0 = 0; f0 < 8; f0++) {
            float a[16];
            #pragma unroll
            for (int i = 0; i < 16; i++) a[i] = zsh[r * ZS + f0 * 16 + i];
            ull pe[8], po[7];
            #pragma unroll
            for (int i = 0; i < 8; i++) pe[i] = pack2(a[2*i], a[2*i+1]);
            #pragma unroll
            for (int i = 0; i < 7; i++) po[i] = pack2(a[2*i+1], a[2*i+2]);

            #pragma unroll
            for (int c = 0; c < 4; c++) {
                const float* wb = w1sh + (fg * 4 + c) * 32 + f0 * 4;
                ull w0 = pack2(wb[0], wb[0]);
                ull w1 = pack2(wb[1], wb[1]);
                ull w2 = pack2(wb[2], wb[2]);
                ull w3 = pack2(wb[3], wb[3]);
                #pragma unroll
                for (int p = 0; p < 6; p++) {
                    acc2[c][p] = ffma2(pe[p],     w0, acc2[c][p]);
                    acc2[c][p] = ffma2(po[p],     w1, acc2[c][p]);
                    acc2[c][p] = ffma2(pe[p + 1], w2, acc2[c][p]);
                    acc2[c][p] = ffma2(po[p + 1], w3, acc2[c][p]);
                }
            }
        }
        #pragma unroll
        for (int c = 0; c < 4; c++) {
            int f1 = fg * 4 + c;
            float bb = b1sh[f1];
            #pragma unroll
            for (int p = 0; p < 6; p++) {
                float v0, v1; unpack2(acc2[c][p], v0, v1);
                v0 = fmaxf(v0 + bb, 0.f);
                v1 = fmaxf(v1 + bb, 0.f);
                y1sh[r * Y1S + f1 * 6 + p] = fmaxf(v0, v1);
            }
        }
    }
    __syncthreads();

    // ---- conv2 + relu + maxpool2 : thread = (r, 8 channels), packed pos-pairs ----
    {
        int r = tid & 31, fg = tid >> 5;       // channels fg*8..+7
        ull acc2[8][2];                        // positions (0,1) and (2,3)
        #pragma unroll
        for (int c = 0; c < 8; c++) { acc2[c][0] = 0ull; acc2[c][1] = 0ull; }

        #pragma unroll 4
        for (int f1 = 0; f1 < 32; f1++) {
            float a[6];
            #pragma unroll
            for (int i = 0; i < 6; i++) a[i] = y1sh[r * Y1S + f1 * 6 + i];
            ull pe0 = pack2(a[0], a[1]);
            ull pe1 = pack2(a[2], a[3]);
            ull pe2 = pack2(a[4], a[5]);
            ull po0 = pack2(a[1], a[2]);
            ull po1 = pack2(a[3], a[4]);

            #pragma unroll
            for (int c = 0; c < 8; c++) {
                const float* wb = w2sh + (fg * 8 + c) * 96 + f1 * 3;
                ull w0 = pack2(wb[0], wb[0]);
                ull w1 = pack2(wb[1], wb[1]);
                ull w2 = pack2(wb[2], wb[2]);
                acc2[c][0] = ffma2(pe0, w0, acc2[c][0]);
                acc2[c][0] = ffma2(po0, w1, acc2[c][0]);
                acc2[c][0] = ffma2(pe1, w2, acc2[c][0]);
                acc2[c][1] = ffma2(pe1, w0, acc2[c][1]);
                acc2[c][1] = ffma2(po1, w1, acc2[c][1]);
                acc2[c][1] = ffma2(pe2, w2, acc2[c][1]);
            }
        }
        #pragma unroll
        for (int c = 0; c < 8; c++) {
            int f2 = fg * 8 + c;
            float bb = b2sh[f2];
            float u0, u1, u2, u3;
            unpack2(acc2[c][0], u0, u1);
            unpack2(acc2[c][1], u2, u3);
            float v0 = fmaxf(fmaxf(u0 + bb, 0.f), fmaxf(u1 + bb, 0.f));
            float v1 = fmaxf(fmaxf(u2 + bb, 0.f), fmaxf(u3 + bb, 0.f));
            y2sh[r * Y2S + f2 * 2 + 0] = v0;   // flatten order d = f2*2 + l
            y2sh[r * Y2S + f2 * 2 + 1] = v1;
        }
    }
    __syncthreads();                           // y1/w1/w2 reads complete

    // ---- stage fc weights (packed) into dead region ----
    {
        ull* fc1wp = reinterpret_cast<ull*>(sm + OFF_FC1W);   // [jp*128 + d]
        for (int i = tid; i < 4096; i += 256) {
            int d  = i & 127;
            int jp = i >> 7;                   // 0..31: outputs (2jp, 2jp+1)
            float lo = f1wg[(2 * jp)     * 128 + d];   // coalesced over d
            float hi = f1wg[(2 * jp + 1) * 128 + d];
            fc1wp[jp * 128 + d] = pack2(lo, hi);
        }
        if (tid < 64)  sm[OFF_FC1B + tid] = f1bg[tid];
        if (tid < 5)   sm[OFF_FC2B + tid] = f2bg[tid];
        for (int i = tid; i < 320; i += 256) sm[OFF_FC2W + i] = f2wg[i];
    }
    __syncthreads();

    // ---- fc1 + relu : 256 threads, tile 2 rows x 4 hidden (2 packed pairs) ----
    {
        const ull* fc1wp = reinterpret_cast<const ull*>(sm + OFF_FC1W);
        const float* fb  = sm + OFF_FC1B;
        int rg = tid & 15;                     // rows rg*2, rg*2+1
        int hg = tid >> 4;                     // hidden hg*4..+3 = jp {2hg,2hg+1}
        ull acc2[2][2];
        acc2[0][0] = acc2[0][1] = acc2[1][0] = acc2[1][1] = 0ull;

        #pragma unroll 4
        for (int d = 0; d < 128; d++) {
            float a0 = y2sh[(rg * 2 + 0) * Y2S + d];
            float a1 = y2sh[(rg * 2 + 1) * Y2S + d];
            ull a0p = pack2(a0, a0);
            ull a1p = pack2(a1, a1);
            ull w01 = fc1wp[(2 * hg)     * 128 + d];   // broadcast (warp-uniform)
            ull w23 = fc1wp[(2 * hg + 1) * 128 + d];
            acc2[0][0] = ffma2(a0p, w01, acc2[0][0]);
            acc2[0][1] = ffma2(a0p, w23, acc2[0][1]);
            acc2[1][0] = ffma2(a1p, w01, acc2[1][0]);
            acc2[1][1] = ffma2(a1p, w23, acc2[1][1]);
        }
        #pragma unroll
        for (int i = 0; i < 2; i++) {
            float h0, h1, h2, h3;
            unpack2(acc2[i][0], h0, h1);
            unpack2(acc2[i][1], h2, h3);
            float* hr = hsh + (rg * 2 + i) * HS + hg * 4;
            hr[0] = fmaxf(h0 + fb[hg * 4 + 0], 0.f);
            hr[1] = fmaxf(h1 + fb[hg * 4 + 1], 0.f);
            hr[2] = fmaxf(h2 + fb[hg * 4 + 2], 0.f);
            hr[3] = fmaxf(h3 + fb[hg * 4 + 3], 0.f);
        }
    }
    __syncthreads();

    // ---- fc2 (packed dot) + transposed output write: out[b,t,o,n] ----
    if (tid < 160) {
        const ull* fc2wp = reinterpret_cast<const ull*>(sm + OFF_FC2W);
        const float* fc2b = sm + OFF_FC2B;
        int r = tid & 31, o = tid >> 5;
        const ull* hp = reinterpret_cast<const ull*>(hsh + r * HS);
        const ull* wp = fc2wp + o * 32;
        ull acc2 = 0ull;
        #pragma unroll 8
        for (int jp = 0; jp < 32; jp++)
            acc2 = ffma2(hp[jp], wp[jp], acc2);
        float lo, hi; unpack2(acc2, lo, hi);
        float acc = lo + hi + fc2b[o];
        int R  = row0 + r;
        int n  = R % NN;
        int bt = R / NN;
        out[((size_t)bt * 5 + o) * NN + n] = acc;
    }
}

// ---------------------------------------------------------------------------
extern "C" void kernel_launch(void* const* d_in, const int* in_sizes, int n_in,
                              void* d_out, int out_size)
{
    const float* x   = (const float*)d_in[0];
    const float* S   = (const float*)d_in[1];
    const float* w1  = (const float*)d_in[2];
    const float* b1  = (const float*)d_in[3];
    const float* w2  = (const float*)d_in[4];
    const float* b2  = (const float*)d_in[5];
    const float* f1w = (const float*)d_in[6];
    const float* f1b = (const float*)d_in[7];
    const float* f2w = (const float*)d_in[8];
    const float* f2b = (const float*)d_in[9];
    float* out = (float*)d_out;

    // 15 sequential diffusion steps (graph replay amortizes launch cost)
    for (int k = 1; k <= 15; k++)
        diffuse_step_kernel<<<BT, 256>>>(x, S, k);

    size_t smem = (size_t)SMEM_FLOATS * sizeof(float);
    cudaFuncSetAttribute(head_kernel,
                         cudaFuncAttributeMaxDynamicSharedMemorySize, (int)smem);
    head_kernel<<<(NB * NT * NN) / 32, 256, smem>>>(
        x, w1, b1, w2, b2, f1w, f1b, f2w, f2b, out);
}

// round 8
// speedup vs baseline: 1.0062x; 1.0062x over previous
#include <cuda_runtime.h>
#include <cstddef>

// Problem constants
#define NB   16
#define NT   64
#define NF0  8
#define NN   100
#define BT   (NB * NT)            // 1024
#define ROWSTRIDE (NF0 * NN)      // 800 floats per (b,t) slice
#define SLAB ((size_t)BT * ROWSTRIDE)  // 819200 floats per k-slab

__device__ float g_z[15 * BT * ROWSTRIDE];   // ~49.15 MB (slabs k=1..15)

// ---- packed f32x2 helpers ----
typedef unsigned long long ull;
__device__ __forceinline__ ull pack2(float lo, float hi) {
    ull r; asm("mov.b64 %0, {%1,%2};" : "=l"(r) : "f"(lo), "f"(hi)); return r;
}
__device__ __forceinline__ void unpack2(ull v, float& lo, float& hi) {
    asm("mov.b64 {%0,%1}, %2;" : "=f"(lo), "=f"(hi) : "l"(v));
}
__device__ __forceinline__ ull ffma2(ull a, ull b, ull c) {
    ull d; asm("fma.rn.f32x2 %0, %1, %2, %3;" : "=l"(d) : "l"(a), "l"(b), "l"(c));
    return d;
}

// ---------------------------------------------------------------------------
// Diffusion step k (R6 version — measured best): one block per (b,t),
// 256 threads (200 active), 1 f-row x 4 m-cols, S float4 stream, unroll 10.
// ---------------------------------------------------------------------------
__global__ __launch_bounds__(256)
void diffuse_step_kernel(const float* __restrict__ x,
                         const float* __restrict__ S,
                         int k)
{
    int bt  = blockIdx.x;
    int t   = bt & 63;
    if (t < k) return;
    int tid = threadIdx.x;

    const float* src = (k == 1)
        ? (x + (size_t)(bt - 1) * ROWSTRIDE)
        : (g_z + (size_t)(k - 2) * SLAB + (size_t)(bt - 1) * ROWSTRIDE);

    __shared__ float Ash[ROWSTRIDE];
    for (int i = tid; i < ROWSTRIDE; i += 256) Ash[i] = src[i];
    __syncthreads();

    if (tid < 200) {
        int mg = tid % 25;
        int f  = tid / 25;
        int m0 = mg * 4;
        const float* A0 = Ash + f * NN;
        const float* Sp = S + (size_t)bt * (NN * NN) + m0;

        float a0 = 0.f, a1 = 0.f, a2 = 0.f, a3 = 0.f;
        #pragma unroll 10
        for (int n = 0; n < NN; n++) {
            float4 s = *reinterpret_cast<const float4*>(Sp + (size_t)n * NN);
            float va = A0[n];
            a0 = fmaf(va, s.x, a0); a1 = fmaf(va, s.y, a1);
            a2 = fmaf(va, s.z, a2); a3 = fmaf(va, s.w, a3);
        }
        float* d = g_z + (size_t)(k - 1) * SLAB + (size_t)bt * ROWSTRIDE
                 + f * NN + m0;
        d[0] = a0; d[1] = a1; d[2] = a2; d[3] = a3;
    }
}

// ---------------------------------------------------------------------------
// Fused head, ROW-PAIR-PACKED: every activation tile stored as float2 of
// (row 2rp, row 2rp+1). Packed FMA2 operands come straight from LDS.64;
// weights pre-packed (w,w) with padded strides (no bank conflicts, no movs).
//
// Smem layout (floats):
//  [0,4096)        zp   [col=f*16+k][rp] float2    -> reused as y2p [d][rp]
//  [4096,10240)    y1p  [col=f1*6+p][rp] float2    -> front reused as hsh(32x66)
//  [10240,12352)   w1p  [c][33: f0*4+k] float2 (padded stride 33)
//  [12352,24768)   w2p  [c][97: f1*3+k] float2 (padded stride 97)
//  [24768,24800)   b1,  [24800,24864) b2
//  after conv2 (y1p/w1p/w2p dead):
//  [6240,14496)    fc1wp [hp=32][129: d] ull (padded)
//  [14496,14560)   fc1b, [14560,14880) fc2w, [14880,14885) fc2b
// ---------------------------------------------------------------------------
#define OFF_Y1P  4096
#define OFF_HSH  4096
#define HS       66
#define OFF_W1P  10240
#define OFF_W2P  12352
#define OFF_B1   24768
#define OFF_B2   24800
#define OFF_FC1W 6240
#define OFF_FC1B 14496
#define OFF_FC2W 14560
#define OFF_FC2B 14880
#define SMEM_FLOATS 24864

__global__ __launch_bounds__(256, 2)
void head_kernel(const float* __restrict__ x,
                 const float* __restrict__ w1g, const float* __restrict__ b1g,
                 const float* __restrict__ w2g, const float* __restrict__ b2g,
                 const float* __restrict__ f1wg, const float* __restrict__ f1bg,
                 const float* __restrict__ f2wg, const float* __restrict__ f2bg,
                 float* __restrict__ out)
{
    extern __shared__ float sm[];
    ull*   zpu  = reinterpret_cast<ull*>(sm);           // zp / y2p (packed)
    ull*   y1pu = reinterpret_cast<ull*>(sm + OFF_Y1P);
    float* hsh  = sm + OFF_HSH;
    const ull* w1pu = reinterpret_cast<const ull*>(sm + OFF_W1P);
    const ull* w2pu = reinterpret_cast<const ull*>(sm + OFF_W2P);
    float* b1sh = sm + OFF_B1;
    float* b2sh = sm + OFF_B2;

    int tid  = threadIdx.x;
    int row0 = blockIdx.x * 32;

    // ---- stage 0: gather z -> row-pair layout zp[col*32 + r] + pack weights ----
    for (int i = tid; i < 4096; i += 256) {
        int r  = i & 31;
        int kf = i >> 5;
        int f  = kf >> 4;
        int k  = kf & 15;
        int R  = row0 + r;
        int n  = R % NN;
        int bt = R / NN;
        float v;
        if (k == 0) {
            v = x[(size_t)bt * ROWSTRIDE + f * NN + n];
        } else if ((bt & 63) < k) {
            v = 0.f;
        } else {
            v = g_z[(size_t)(k - 1) * SLAB + (size_t)bt * ROWSTRIDE + f * NN + n];
        }
        sm[(f * 16 + k) * 32 + r] = v;   // = zp[col][rp] float2, parity r&1
    }
    {   // w1 packed (w,w), channel stride 33 ull
        ull* w1w = reinterpret_cast<ull*>(sm + OFF_W1P);
        for (int i = tid; i < 1024; i += 256) {
            int c = i >> 5, rmn = i & 31;
            float v = w1g[i];
            w1w[c * 33 + rmn] = pack2(v, v);
        }
        // w2 packed (w,w), channel stride 97 ull
        ull* w2w = reinterpret_cast<ull*>(sm + OFF_W2P);
        for (int i = tid; i < 6144; i += 256) {
            int c = i / 96, rmn = i % 96;
            float v = w2g[i];
            w2w[c * 97 + rmn] = pack2(v, v);
        }
        if (tid < 32) b1sh[tid] = b1g[tid];
        if (tid < 64) b2sh[tid] = b2g[tid];
    }
    __syncthreads();

    // ---- conv1 + relu + pool2 : thread = (rp, fg), 2 channels, rows packed ----
    {
        int rp = tid & 15, fg = tid >> 4;        // fg in [0,16): channels fg*2..+1
        ull acc2[2][12];
        #pragma unroll
        for (int c = 0; c < 2; c++)
            #pragma unroll
            for (int p = 0; p < 12; p++) acc2[c][p] = 0ull;

        #pragma unroll 2
        for (int f0 = 0; f0 < 8; f0++) {
            ull ap[16];
            #pragma unroll
            for (int i = 0; i < 16; i++) ap[i] = zpu[(f0 * 16 + i) * 16 + rp];
            #pragma unroll
            for (int c = 0; c < 2; c++) {
                int ch = fg * 2 + c;
                #pragma unroll
                for (int kk = 0; kk < 4; kk++) {
                    ull w = w1pu[ch * 33 + f0 * 4 + kk];
                    #pragma unroll
                    for (int p = 0; p < 12; p++)
                        acc2[c][p] = ffma2(ap[p + kk], w, acc2[c][p]);
                }
            }
        }
        #pragma unroll
        for (int c = 0; c < 2; c++) {
            int f1 = fg * 2 + c;
            float bb = b1sh[f1];
            #pragma unroll
            for (int pp = 0; pp < 6; pp++) {
                float alo, ahi, blo, bhi;
                unpack2(acc2[c][2 * pp],     alo, ahi);
                unpack2(acc2[c][2 * pp + 1], blo, bhi);
                float lo = fmaxf(fmaxf(alo + bb, 0.f), fmaxf(blo + bb, 0.f));
                float hi = fmaxf(fmaxf(ahi + bb, 0.f), fmaxf(bhi + bb, 0.f));
                y1pu[(f1 * 6 + pp) * 16 + rp] = pack2(lo, hi);
            }
        }
    }
    __syncthreads();

    // ---- conv2 + relu + pool2 : 128 threads = (rp, cg), 8 channels each ----
    if (tid < 128) {
        int rp = tid & 15, cg = tid >> 4;        // cg in [0,8): channels cg*8..+7
        int c0 = cg * 8;
        ull acc2[8][4];
        #pragma unroll
        for (int c = 0; c < 8; c++)
            #pragma unroll
            for (int p = 0; p < 4; p++) acc2[c][p] = 0ull;

        #pragma unroll 4
        for (int f1 = 0; f1 < 32; f1++) {
            ull ap[6];
            #pragma unroll
            for (int i = 0; i < 6; i++) ap[i] = y1pu[(f1 * 6 + i) * 16 + rp];
            #pragma unroll
            for (int c = 0; c < 8; c++) {
                const ull* wb = w2pu + (c0 + c) * 97 + f1 * 3;
                ull w0 = wb[0], w1 = wb[1], w2 = wb[2];
                #pragma unroll
                for (int p = 0; p < 4; p++) {
                    acc2[c][p] = ffma2(ap[p],     w0, acc2[c][p]);
                    acc2[c][p] = ffma2(ap[p + 1], w1, acc2[c][p]);
                    acc2[c][p] = ffma2(ap[p + 2], w2, acc2[c][p]);
                }
            }
        }
        #pragma unroll
        for (int c = 0; c < 8; c++) {
            int f2 = c0 + c;
            float bb = b2sh[f2];
            float u0l,u0h,u1l,u1h,u2l,u2h,u3l,u3h;
            unpack2(acc2[c][0], u0l, u0h);
            unpack2(acc2[c][1], u1l, u1h);
            unpack2(acc2[c][2], u2l, u2h);
            unpack2(acc2[c][3], u3l, u3h);
            float v0l = fmaxf(fmaxf(u0l + bb, 0.f), fmaxf(u1l + bb, 0.f));
            float v0h = fmaxf(fmaxf(u0h + bb, 0.f), fmaxf(u1h + bb, 0.f));
            float v1l = fmaxf(fmaxf(u2l + bb, 0.f), fmaxf(u3l + bb, 0.f));
            float v1h = fmaxf(fmaxf(u2h + bb, 0.f), fmaxf(u3h + bb, 0.f));
            zpu[(f2 * 2 + 0) * 16 + rp] = pack2(v0l, v0h);   // y2p (zp reused)
            zpu[(f2 * 2 + 1) * 16 + rp] = pack2(v1l, v1h);
        }
    }
    __syncthreads();                             // y1p/w1p/w2p now dead

    // ---- stage fc weights into dead region ----
    {
        ull* fc1wp = reinterpret_cast<ull*>(sm + OFF_FC1W);  // [jp*129 + d]
        for (int i = tid; i < 4096; i += 256) {
            int d  = i & 127;
            int jp = i >> 7;
            float lo = f1wg[(2 * jp)     * 128 + d];
            float hi = f1wg[(2 * jp + 1) * 128 + d];
            fc1wp[jp * 129 + d] = pack2(lo, hi);
        }
        if (tid < 64) sm[OFF_FC1B + tid] = f1bg[tid];
        if (tid < 5)  sm[OFF_FC2B + tid] = f2bg[tid];
        for (int i = tid; i < 320; i += 256) sm[OFF_FC2W + i] = f2wg[i];
    }
    __syncthreads();

    // ---- fc1 + relu : 128 threads, 4 rows x 4 hidden (2 packed h-pairs) ----
    if (tid < 128) {
        const ull* fc1wp = reinterpret_cast<const ull*>(sm + OFF_FC1W);
        const float* fb  = sm + OFF_FC1B;
        int rg = tid & 7;                        // rows rg*4..+3
        int hg = tid >> 3;                       // hidden hg*4..+3
        ull acc2[4][2];
        #pragma unroll
        for (int i = 0; i < 4; i++) { acc2[i][0] = 0ull; acc2[i][1] = 0ull; }

        #pragma unroll 4
        for (int d = 0; d < 128; d++) {
            ull w01 = fc1wp[(2 * hg)     * 129 + d];
            ull w23 = fc1wp[(2 * hg + 1) * 129 + d];
            #pragma unroll
            for (int i = 0; i < 4; i++) {
                float a = sm[d * 32 + rg * 4 + i];   // y2p scalar view
                ull ap = pack2(a, a);
                acc2[i][0] = ffma2(ap, w01, acc2[i][0]);
                acc2[i][1] = ffma2(ap, w23, acc2[i][1]);
            }
        }
        #pragma unroll
        for (int i = 0; i < 4; i++) {
            float h0, h1, h2, h3;
            unpack2(acc2[i][0], h0, h1);
            unpack2(acc2[i][1], h2, h3);
            float* hr = hsh + (rg * 4 + i) * HS + hg * 4;
            hr[0] = fmaxf(h0 + fb[hg * 4 + 0], 0.f);
            hr[1] = fmaxf(h1 + fb[hg * 4 + 1], 0.f);
            hr[2] = fmaxf(h2 + fb[hg * 4 + 2], 0.f);
            hr[3] = fmaxf(h3 + fb[hg * 4 + 3], 0.f);
        }
    }
    __syncthreads();

    // ---- fc2 (packed dot) + transposed output write: out[b,t,o,n] ----
    if (tid < 160) {
        const ull* fc2wp = reinterpret_cast<const ull*>(sm + OFF_FC2W);
        const float* fc2b = sm + OFF_FC2B;
        int r = tid & 31, o = tid >> 5;
        const ull* hp = reinterpret_cast<const ull*>(hsh + r * HS);
        const ull* wp = fc2wp + o * 32;
        ull acc2 = 0ull;
        #pragma unroll 8
        for (int jp = 0; jp < 32; jp++)
            acc2 = ffma2(hp[jp], wp[jp], acc2);
        float lo, hi; unpack2(acc2, lo, hi);
        float acc = lo + hi + fc2b[o];
        int R  = row0 + r;
        int n  = R % NN;
        int bt = R / NN;
        out[((size_t)bt * 5 + o) * NN + n] = acc;
    }
}

// ---------------------------------------------------------------------------
extern "C" void kernel_launch(void* const* d_in, const int* in_sizes, int n_in,
                              void* d_out, int out_size)
{
    const float* x   = (const float*)d_in[0];
    const float* S   = (const float*)d_in[1];
    const float* w1  = (const float*)d_in[2];
    const float* b1  = (const float*)d_in[3];
    const float* w2  = (const float*)d_in[4];
    const float* b2  = (const float*)d_in[5];
    const float* f1w = (const float*)d_in[6];
    const float* f1b = (const float*)d_in[7];
    const float* f2w = (const float*)d_in[8];
    const float* f2b = (const float*)d_in[9];
    float* out = (float*)d_out;

    for (int k = 1; k <= 15; k++)
        diffuse_step_kernel<<<BT, 256>>>(x, S, k);

    size_t smem = (size_t)SMEM_FLOATS * sizeof(float);
    cudaFuncSetAttribute(head_kernel,
                         cudaFuncAttributeMaxDynamicSharedMemorySize, (int)smem);
    head_kernel<<<(NB * NT * NN) / 32, 256, smem>>>(
        x, w1, b1, w2, b2, f1w, f1b, f2w, f2b, out);
}

// round 9
// speedup vs baseline: 1.1972x; 1.1899x over previous
#include <cuda_runtime.h>
#include <cstddef>

// Problem constants
#define NB   16
#define NT   64
#define NF0  8
#define NN   100
#define BT   (NB * NT)            // 1024
#define ROWSTRIDE (NF0 * NN)      // 800 floats per (b,t) slice
#define SLAB ((size_t)BT * ROWSTRIDE)  // 819200 floats per k-slab

__device__ float g_z[15 * BT * ROWSTRIDE];   // slabs k=1..15 (~49 MB)

// ---- packed f32x2 helpers ----
typedef unsigned long long ull;
__device__ __forceinline__ ull pack2(float lo, float hi) {
    ull r; asm("mov.b64 %0, {%1,%2};" : "=l"(r) : "f"(lo), "f"(hi)); return r;
}
__device__ __forceinline__ void unpack2(ull v, float& lo, float& hi) {
    asm("mov.b64 {%0,%1}, %2;" : "=f"(lo), "=f"(hi) : "l"(v));
}
__device__ __forceinline__ ull ffma2(ull a, ull b, ull c) {
    ull d; asm("fma.rn.f32x2 %0, %1, %2, %3;" : "=l"(d) : "l"(a), "l"(b), "l"(c));
    return d;
}

// ---------------------------------------------------------------------------
// Diffusion step k, WAVEFRONT-MINIMAL mapping:
// thread = output column m (tid<100), owns all 8 f accumulators (4 x f32x2).
// Per n: scalar coalesced S load (1-2 wf) + 2 broadcast LDS.128 of transposed
// A row (1 wf each) + 4 FMA2.  A stored transposed [n][f] in smem.
// ---------------------------------------------------------------------------
__global__ __launch_bounds__(128)
void diffuse_step_kernel(const float* __restrict__ x,
                         const float* __restrict__ S,
                         int k)
{
    int bt  = blockIdx.x;          // b*64 + t
    int t   = bt & 63;
    if (t < k) return;             // triangular zero region: never stored
    int tid = threadIdx.x;

    const float* src = (k == 1)
        ? (x + (size_t)(bt - 1) * ROWSTRIDE)
        : (g_z + (size_t)(k - 2) * SLAB + (size_t)(bt - 1) * ROWSTRIDE);

    __shared__ float At[NN * NF0];            // [n][f], 16B-aligned rows
    for (int i = tid; i < ROWSTRIDE; i += 128) {
        int f = i / NN, n = i % NN;
        At[n * 8 + f] = src[i];               // coalesced read, strided write
    }
    __syncthreads();

    if (tid < 100) {
        int m = tid;
        const float* Sp = S + (size_t)bt * (NN * NN) + m;

        ull acc01 = 0ull, acc23 = 0ull, acc45 = 0ull, acc67 = 0ull;
        #pragma unroll 4
        for (int n = 0; n < NN; n++) {
            float s = Sp[(size_t)n * NN];     // coalesced across lanes
            ull s2 = pack2(s, s);
            const ull* ar = reinterpret_cast<const ull*>(At + n * 8);
            ull a01 = ar[0], a23 = ar[1], a45 = ar[2], a67 = ar[3];
            acc01 = ffma2(a01, s2, acc01);
            acc23 = ffma2(a23, s2, acc23);
            acc45 = ffma2(a45, s2, acc45);
            acc67 = ffma2(a67, s2, acc67);
        }
        float* dst = g_z + (size_t)(k - 1) * SLAB + (size_t)bt * ROWSTRIDE + m;
        float v0, v1;
        unpack2(acc01, v0, v1); dst[0 * NN] = v0; dst[1 * NN] = v1;
        unpack2(acc23, v0, v1); dst[2 * NN] = v0; dst[3 * NN] = v1;
        unpack2(acc45, v0, v1); dst[4 * NN] = v0; dst[5 * NN] = v1;
        unpack2(acc67, v0, v1); dst[6 * NN] = v0; dst[7 * NN] = v1;
    }
}

// ---------------------------------------------------------------------------
// Fused head (proven R2/R3 scalar version, ~342us):
// gather z [8][16] -> conv1(K=4)+relu+pool2 -> [32][6]
// -> conv2(K=3)+relu+pool2 -> [64][2] -> fc1(128->64)+relu -> fc2(64->5)
// 32 rows/block, 256 threads, 2 blocks/SM, stage-overlaid smem.
// ---------------------------------------------------------------------------
#define ZS   129
#define Y1S  193
#define Y2S  129
#define HS   65
#define OFF_HSH 4128
#define OFF_Y1  6208
#define OFF_W1  12384
#define OFF_B1  13408
#define OFF_W2  13440
#define SMEM_FLOATS 22085

__global__ __launch_bounds__(256, 2)
void head_kernel(const float* __restrict__ x,
                 const float* __restrict__ w1g, const float* __restrict__ b1g,
                 const float* __restrict__ w2g, const float* __restrict__ b2g,
                 const float* __restrict__ f1wg, const float* __restrict__ f1bg,
                 const float* __restrict__ f2wg, const float* __restrict__ f2bg,
                 float* __restrict__ out)
{
    extern __shared__ float sm[];
    float* zsh  = sm;
    float* y2sh = sm;                 // reuses zsh region after conv1
    float* hsh  = sm + OFF_HSH;
    float* y1sh = sm + OFF_Y1;
    float* w1sh = sm + OFF_W1;
    float* b1sh = sm + OFF_B1;

    int tid  = threadIdx.x;
    int row0 = blockIdx.x * 32;       // global row = (b*T + t)*N + n

    // ---- stage 0: gather z tile (32 rows x 8 f x 16 k) + conv weights ----
    for (int i = tid; i < 4096; i += 256) {
        int r  = i & 31;
        int kf = i >> 5;
        int f  = kf >> 4;
        int k  = kf & 15;
        int R  = row0 + r;
        int n  = R % NN;
        int bt = R / NN;
        float v;
        if (k == 0) {
            v = x[(size_t)bt * ROWSTRIDE + f * NN + n];
        } else if ((bt & 63) < k) {
            v = 0.f;                  // triangular zero region
        } else {
            v = g_z[(size_t)(k - 1) * SLAB + (size_t)bt * ROWSTRIDE + f * NN + n];
        }
        zsh[r * ZS + f * 16 + k] = v;
    }
    for (int i = tid; i < 1024; i += 256) w1sh[i] = w1g[i];
    if (tid < 32) b1sh[tid] = b1g[tid];
    {
        float* w2sh = sm + OFF_W2;
        for (int i = tid; i < 6144; i += 256) w2sh[i] = w2g[i];
        if (tid < 64) w2sh[6144 + tid] = b2g[tid];
    }
    __syncthreads();

    // ---- conv1 + relu + maxpool2 : thread = (r, 4 channels) ----
    {
        int r = tid & 31, fg = tid >> 5;
        float acc[4][12];
        #pragma unroll
        for (int c = 0; c < 4; c++)
            #pragma unroll
            for (int l = 0; l < 12; l++) acc[c][l] = 0.f;

        #pragma unroll 2
        for (int f0 = 0; f0 < 8; f0++) {
            float a[16];
            #pragma unroll
            for (int i = 0; i < 16; i++) a[i] = zsh[r * ZS + f0 * 16 + i];
            #pragma unroll
            for (int kk = 0; kk < 4; kk++) {
                #pragma unroll
                for (int c = 0; c < 4; c++) {
                    float w = w1sh[(fg * 4 + c) * 32 + f0 * 4 + kk];
                    #pragma unroll
                    for (int l = 0; l < 12; l++)
                        acc[c][l] = fmaf(a[l + kk], w, acc[c][l]);
                }
            }
        }
        #pragma unroll
        for (int c = 0; c < 4; c++) {
            int f1 = fg * 4 + c;
            float bb = b1sh[f1];
            #pragma unroll
            for (int lp = 0; lp < 6; lp++) {
                float v0 = fmaxf(acc[c][2 * lp]     + bb, 0.f);
                float v1 = fmaxf(acc[c][2 * lp + 1] + bb, 0.f);
                y1sh[r * Y1S + f1 * 6 + lp] = fmaxf(v0, v1);
            }
        }
    }
    __syncthreads();

    // ---- conv2 + relu + maxpool2 : thread = (r, 8 channels) ----
    {
        const float* w2sh = sm + OFF_W2;
        const float* b2sh = w2sh + 6144;
        int r = tid & 31, fg = tid >> 5;
        float acc[8][4];
        #pragma unroll
        for (int c = 0; c < 8; c++)
            #pragma unroll
            for (int l = 0; l < 4; l++) acc[c][l] = 0.f;

        #pragma unroll 4
        for (int f1 = 0; f1 < 32; f1++) {
            float a[6];
            #pragma unroll
            for (int i = 0; i < 6; i++) a[i] = y1sh[r * Y1S + f1 * 6 + i];
            #pragma unroll
            for (int kk = 0; kk < 3; kk++) {
                #pragma unroll
                for (int c = 0; c < 8; c++) {
                    float w = w2sh[(fg * 8 + c) * 96 + f1 * 3 + kk];
                    #pragma unroll
                    for (int l = 0; l < 4; l++)
                        acc[c][l] = fmaf(a[l + kk], w, acc[c][l]);
                }
            }
        }
        #pragma unroll
        for (int c = 0; c < 8; c++) {
            int f2 = fg * 8 + c;
            float bb = b2sh[f2];
            float v0 = fmaxf(fmaxf(acc[c][0] + bb, 0.f), fmaxf(acc[c][1] + bb, 0.f));
            float v1 = fmaxf(fmaxf(acc[c][2] + bb, 0.f), fmaxf(acc[c][3] + bb, 0.f));
            y2sh[r * Y2S + f2 * 2 + 0] = v0;
            y2sh[r * Y2S + f2 * 2 + 1] = v1;
        }
    }
    __syncthreads();

    // ---- load fc weights (overwrites conv2 weight region) ----
    {
        float* fcr = sm + OFF_W2;
        for (int i = tid; i < 8192; i += 256) {
            int j = i >> 7, d = i & 127;
            fcr[j * 129 + d] = f1wg[i];
        }
        if (tid < 64) fcr[8256 + tid] = f1bg[tid];
        for (int i = tid; i < 320; i += 256) fcr[8320 + i] = f2wg[i];
        if (tid < 5) fcr[8640 + tid] = f2bg[tid];
    }
    __syncthreads();

    // ---- fc1 + relu : 128 threads, thread tile 4 rows x 4 hidden ----
    if (tid < 128) {
        const float* fc1sh = sm + OFF_W2;
        const float* fb    = fc1sh + 8256;
        int rg = tid & 7;
        int hg = tid >> 3;
        float acc[4][4];
        #pragma unroll
        for (int i = 0; i < 4; i++)
            #pragma unroll
            for (int j = 0; j < 4; j++) acc[i][j] = 0.f;

        #pragma unroll 4
        for (int d = 0; d < 128; d++) {
            float a0 = y2sh[(rg * 4 + 0) * Y2S + d];
            float a1 = y2sh[(rg * 4 + 1) * Y2S + d];
            float a2 = y2sh[(rg * 4 + 2) * Y2S + d];
            float a3 = y2sh[(rg * 4 + 3) * Y2S + d];
            float w0 = fc1sh[(hg * 4 + 0) * 129 + d];
            float w1 = fc1sh[(hg * 4 + 1) * 129 + d];
            float w2 = fc1sh[(hg * 4 + 2) * 129 + d];
            float w3 = fc1sh[(hg * 4 + 3) * 129 + d];
            acc[0][0] = fmaf(a0, w0, acc[0][0]); acc[0][1] = fmaf(a0, w1, acc[0][1]);
            acc[0][2] = fmaf(a0, w2, acc[0][2]); acc[0][3] = fmaf(a0, w3, acc[0][3]);
            acc[1][0] = fmaf(a1, w0, acc[1][0]); acc[1][1] = fmaf(a1, w1, acc[1][1]);
            acc[1][2] = fmaf(a1, w2, acc[1][2]); acc[1][3] = fmaf(a1, w3, acc[1][3]);
            acc[2][0] = fmaf(a2, w0, acc[2][0]); acc[2][1] = fmaf(a2, w1, acc[2][1]);
            acc[2][2] = fmaf(a2, w2, acc[2][2]); acc[2][3] = fmaf(a2, w3, acc[2][3]);
            acc[3][0] = fmaf(a3, w0, acc[3][0]); acc[3][1] = fmaf(a3, w1, acc[3][1]);
            acc[3][2] = fmaf(a3, w2, acc[3][2]); acc[3][3] = fmaf(a3, w3, acc[3][3]);
        }
        #pragma unroll
        for (int i = 0; i < 4; i++)
            #pragma unroll
            for (int j = 0; j < 4; j++)
                hsh[(rg * 4 + i) * HS + hg * 4 + j] =
                    fmaxf(acc[i][j] + fb[hg * 4 + j], 0.f);
    }
    __syncthreads();

    // ---- fc2 + transposed output write: out[b,t,o,n] ----
    if (tid < 160) {
        const float* fc2w = sm + OFF_W2 + 8320;
        const float* fc2b = sm + OFF_W2 + 8640;
        int r = tid & 31, o = tid >> 5;
        float acc = fc2b[o];
        #pragma unroll 8
        for (int j = 0; j < 64; j++)
            acc = fmaf(hsh[r * HS + j], fc2w[o * 64 + j], acc);
        int R  = row0 + r;
        int n  = R % NN;
        int bt = R / NN;
        out[((size_t)bt * 5 + o) * NN + n] = acc;
    }
}

// ---------------------------------------------------------------------------
extern "C" void kernel_launch(void* const* d_in, const int* in_sizes, int n_in,
                              void* d_out, int out_size)
{
    const float* x   = (const float*)d_in[0];
    const float* S   = (const float*)d_in[1];
    const float* w1  = (const float*)d_in[2];
    const float* b1  = (const float*)d_in[3];
    const float* w2  = (const float*)d_in[4];
    const float* b2  = (const float*)d_in[5];
    const float* f1w = (const float*)d_in[6];
    const float* f1b = (const float*)d_in[7];
    const float* f2w = (const float*)d_in[8];
    const float* f2b = (const float*)d_in[9];
    float* out = (float*)d_out;

    for (int k = 1; k <= 15; k++)
        diffuse_step_kernel<<<BT, 128>>>(x, S, k);

    size_t smem = (size_t)SMEM_FLOATS * sizeof(float);
    cudaFuncSetAttribute(head_kernel,
                         cudaFuncAttributeMaxDynamicSharedMemorySize, (int)smem);
    head_kernel<<<(NB * NT * NN) / 32, 256, smem>>>(
        x, w1, b1, w2, b2, f1w, f1b, f2w, f2b, out);
}